// round 17
// baseline (speedup 1.0000x reference)
#include <cuda_runtime.h>
#include <cstdint>

// out = y * (mean(x,-1) + mean(y,-1)),  [64, 36, 4096] fp32, rows = 2304.
//
// R17: the one unmeasured cell — persistent kernel at SIX CTAs/SM with
// prefetch-1 using a SINGLE 33 KB buffer set. Key insight: the sx buffer
// drains immediately after the x reduction, and sy drains at the reduction
// barrier, so each can be refilled for row k+stride in the middle of row k.
// Grid = 888 = exactly one wave (6 x 148): no wave quantization, prologue
// amortized over 2-3 rows, 6 rows in flight (the best measured cold-BW
// point), TMA issued ahead of every wait. Loads plain TMA, stores __stcs
// (both policy sweeps complete).

constexpr int L_LEN     = 4096;
constexpr int NTHREADS  = 256;
constexpr int NWARPS    = NTHREADS / 32;
constexpr int ITERS     = L_LEN / (NTHREADS * 4);   // 4 float4 per thread
constexpr int ROW_BYTES = L_LEN * 4;                // 16 KB

__device__ __forceinline__ uint32_t smem_u32(const void* p) {
    return (uint32_t)__cvta_generic_to_shared(p);
}

__device__ __forceinline__ void mbar_init(uint32_t mbar, uint32_t count) {
    asm volatile("mbarrier.init.shared.b64 [%0], %1;" :: "r"(mbar), "r"(count) : "memory");
}

__device__ __forceinline__ void mbar_expect_tx(uint32_t mbar, uint32_t bytes) {
    asm volatile("mbarrier.arrive.expect_tx.shared.b64 _, [%0], %1;"
                 :: "r"(mbar), "r"(bytes) : "memory");
}

__device__ __forceinline__ void bulk_ld(uint32_t dst_smem, const void* src, uint32_t bytes,
                                        uint32_t mbar) {
    asm volatile(
        "cp.async.bulk.shared::cluster.global.mbarrier::complete_tx::bytes "
        "[%0], [%1], %2, [%3];"
        :: "r"(dst_smem), "l"(src), "r"(bytes), "r"(mbar) : "memory");
}

__device__ __forceinline__ void mbar_wait(uint32_t mbar, uint32_t parity) {
    uint32_t done;
    asm volatile(
        "{\n\t"
        ".reg .pred p;\n\t"
        "mbarrier.try_wait.parity.acquire.cta.shared::cta.b64 p, [%1], %2;\n\t"
        "selp.b32 %0, 1, 0, p;\n\t"
        "}"
        : "=r"(done) : "r"(mbar), "r"(parity) : "memory");
    if (!done) {
        asm volatile(
            "{\n\t"
            ".reg .pred P1;\n\t"
            "WAIT_LOOP_%=:\n\t"
            "mbarrier.try_wait.parity.acquire.cta.shared::cta.b64 P1, [%0], %1, 0x989680;\n\t"
            "@P1 bra.uni WAIT_DONE_%=;\n\t"
            "bra.uni WAIT_LOOP_%=;\n\t"
            "WAIT_DONE_%=:\n\t"
            "}"
            :: "r"(mbar), "r"(parity) : "memory");
    }
}

__global__ __launch_bounds__(NTHREADS)
void spo2_pp6_kernel(const float* __restrict__ x,
                     const float* __restrict__ y,
                     float* __restrict__ out,
                     int nrows)
{
    __shared__ alignas(128) float sx[L_LEN];            // 16 KB
    __shared__ alignas(128) float sy[L_LEN];            // 16 KB
    __shared__ alignas(8) unsigned long long mbar_storage[2];
    __shared__ float warpsum[NWARPS];

    const int tid = threadIdx.x;
    const int wid = tid >> 5;
    const uint32_t mbx = smem_u32(&mbar_storage[0]);
    const uint32_t mby = smem_u32(&mbar_storage[1]);

    if (tid == 0) {
        mbar_init(mbx, 1);
        mbar_init(mby, 1);
    }
    __syncthreads();

    const int stride = gridDim.x;
    const int row0 = blockIdx.x;

    // Prologue: issue row0's x and y.
    if (tid == 0 && row0 < nrows) {
        const size_t base = (size_t)row0 * L_LEN;
        mbar_expect_tx(mbx, ROW_BYTES);
        bulk_ld(smem_u32(sx), x + base, ROW_BYTES, mbx);
        mbar_expect_tx(mby, ROW_BYTES);
        bulk_ld(smem_u32(sy), y + base, ROW_BYTES, mby);
    }

    int k = 0;
    for (int row = row0; row < nrows; row += stride, k++) {
        const int ph = k & 1;
        const int nrow = row + stride;

        // ---- x: wait, reduce, then refill sx for the NEXT row ----
        mbar_wait(mbx, ph);

        const float4* sx4 = reinterpret_cast<const float4*>(sx);
        float t = 0.0f;
#pragma unroll
        for (int i = 0; i < ITERS; i++) {
            float4 a = sx4[i * NTHREADS + tid];
            t += (a.x + a.y) + (a.z + a.w);
        }

        __syncthreads();   // all reads of sx complete -> safe to refill
        if (tid == 0 && nrow < nrows) {
            mbar_expect_tx(mbx, ROW_BYTES);
            bulk_ld(smem_u32(sx), x + (size_t)nrow * L_LEN, ROW_BYTES, mbx);
        }

        // ---- y: wait, copy to regs + reduce ----
        mbar_wait(mby, ph);

        const float4* sy4 = reinterpret_cast<const float4*>(sy);
        float4 yv[ITERS];
#pragma unroll
        for (int i = 0; i < ITERS; i++) {
            yv[i] = sy4[i * NTHREADS + tid];
            t += (yv[i].x + yv[i].y) + (yv[i].z + yv[i].w);
        }

        // One-barrier block reduction; this barrier also proves every
        // thread's sy reads are done -> refill sy for the next row after it.
#pragma unroll
        for (int o = 16; o > 0; o >>= 1)
            t += __shfl_xor_sync(0xffffffffu, t, o);
        if ((tid & 31) == 0)
            warpsum[wid] = t;
        __syncthreads();

        if (tid == 0 && nrow < nrows) {
            mbar_expect_tx(mby, ROW_BYTES);
            bulk_ld(smem_u32(sy), y + (size_t)nrow * L_LEN, ROW_BYTES, mby);
        }

        float s = 0.0f;
#pragma unroll
        for (int w = 0; w < NWARPS; w++)
            s += warpsum[w];
        const float sc = s * (1.0f / (float)L_LEN);

        // Streaming (evict-first) stores — measured-optimal policy.
        float4* orow = reinterpret_cast<float4*>(out + (size_t)row * L_LEN);
#pragma unroll
        for (int i = 0; i < ITERS; i++) {
            float4 v = yv[i];
            v.x *= sc; v.y *= sc; v.z *= sc; v.w *= sc;
            __stcs(&orow[i * NTHREADS + tid], v);
        }
    }
}

extern "C" void kernel_launch(void* const* d_in, const int* in_sizes, int n_in,
                              void* d_out, int out_size)
{
    const float* x = (const float*)d_in[0];
    const float* y = (const float*)d_in[1];
    float* out = (float*)d_out;

    const int nrows = in_sizes[0] / L_LEN;   // 2304

    int grid = 6 * 148;                      // 888 = one full wave at 6 CTAs/SM
    if (grid > nrows) grid = nrows;
    spo2_pp6_kernel<<<grid, NTHREADS>>>(x, y, out, nrows);
}